// round 17
// baseline (speedup 1.0000x reference)
#include <cuda_runtime.h>
#include <cstdint>

// Causal unbiased-EMA instance norm, x: [B=8, C=256, T=16384] fp32 — EXACT
// via per-lane affine prefix scan, warp-autonomous dataflow.
//
//   s1 = a*s1 + (1-a)*x ; s2 = a*s2 + (1-a)*x^2 ; w = a*w + (1-a)  (= 1-a^t)
//   y  = (w*x - s1) * rsqrt(w*s2 + eps*w^2 - s1^2)
//
// R17 = R12/R16 champion + (a) group-staggered pass 1: the warp's 16
// cp.asyncs keep the SAME ascending global order but commit in two groups of
// 8; after wait_group(1)+syncwarp lanes 0-15 (whose rows live in group 0)
// run pass 1 while the second 4KB is still in flight. (b) ema_step_1 drops
// the cancellation guard (saturated path has d_true >= eps, guard can't fire).
//
// Structure: 8 warps per block own 2048-float segments end-to-end; cross-warp
// affine prefix via flag-chained smem relay; only __syncthreads is the flag
// reset at entry (graph replays leave stale smem).

#define T_LEN  16384
#define TPB    256
#define KP     (T_LEN / TPB)     // 64 steps per thread
#define NWARP  (TPB / 32)        // 8
#define WSEG   (T_LEN / NWARP)   // 2048 floats per warp

#define ALPHA_F 0.99f
#define OMA_F   0.01f
#define EPS_F   1e-5f
#define A64_F   0.52559649f      // 0.99^64
#define W1_TID  28               // tid >= 28 -> t0 >= 1792 -> w == 1.0f

#define PAD(i)  ((i) + (((i) >> 6) << 2))      // +4 floats (16B) per 64-row
#define SMEM_F  (T_LEN + ((T_LEN >> 6) << 2))  // 17408 floats = 69632 B

__device__ __forceinline__ void cp_async16(float* smem_dst, const float* gmem_src) {
    uint32_t s = (uint32_t)__cvta_generic_to_shared(smem_dst);
    asm volatile("cp.async.cg.shared.global [%0], [%1], 16;" :: "r"(s), "l"(gmem_src));
}

__host__ __device__ constexpr float apow(int n) {
    float r = 1.0f;
    for (int i = 0; i < n; i++) r *= ALPHA_F;
    return r;
}

// pass-1 dot product, fully unrolled with constant weights; two accumulator
// pairs for ILP.  c_i = 0.01 * a^(KP-1-i).
template<int I>
__device__ __forceinline__ void warm_unroll(const float4* row,
                                            float& a0, float& b0,
                                            float& a1, float& b1) {
    if constexpr (I < KP / 4) {
        float4 v = row[I];
        constexpr float c0 = OMA_F * apow(KP - 1 - (4 * I + 0));
        constexpr float c1 = OMA_F * apow(KP - 1 - (4 * I + 1));
        constexpr float c2 = OMA_F * apow(KP - 1 - (4 * I + 2));
        constexpr float c3 = OMA_F * apow(KP - 1 - (4 * I + 3));
        float t0 = c0 * v.x;  a0 += t0;  b0 = fmaf(t0, v.x, b0);
        float t1 = c1 * v.y;  a1 += t1;  b1 = fmaf(t1, v.y, b1);
        float t2 = c2 * v.z;  a0 += t2;  b0 = fmaf(t2, v.z, b0);
        float t3 = c3 * v.w;  a1 += t3;  b1 = fmaf(t3, v.w, b1);
        warm_unroll<I + 1>(row, a0, b0, a1, b1);
    }
}

// full step: w still evolving (threads with t0 < 1792; t=1 guard needed)
__device__ __forceinline__ float ema_step_w(float xi, float& s1, float& s2, float& w) {
    float t = OMA_F * xi;
    s1 = fmaf(ALPHA_F, s1, t);
    s2 = fmaf(ALPHA_F, s2, t * xi);
    w  = fmaf(ALPHA_F, w, OMA_F);
    float num = fmaf(w, xi, -s1);
    float e   = fmaf(EPS_F, w, s2);
    float d   = fmaf(w, e, -(s1 * s1));
    d = fmaxf(d, 1e-10f);
    float r;
    asm("rsqrt.approx.f32 %0, %1;" : "=f"(r) : "f"(d));
    return num * r;
}

// saturated step: w == 1.0f exactly (t0 >= 1792). d_true >= eps = 1e-5 here,
// far above rounding noise -> no cancellation guard needed.
__device__ __forceinline__ float ema_step_1(float xi, float& s1, float& s2) {
    float t = OMA_F * xi;
    s1 = fmaf(ALPHA_F, s1, t);
    s2 = fmaf(ALPHA_F, s2, t * xi);
    float num = xi - s1;
    float e   = s2 + EPS_F;
    float d   = fmaf(-s1, s1, e);
    float r;
    asm("rsqrt.approx.f32 %0, %1;" : "=f"(r) : "f"(d));
    return num * r;
}

extern __shared__ float s_buf[];

__global__ void __launch_bounds__(TPB)
ema_norm_kernel(const float* __restrict__ x, float* __restrict__ y)
{
    __shared__ volatile float pub1[NWARP], pub2[NWARP], pubm[NWARP];
    __shared__ volatile int   flag[NWARP];

    const int tid  = threadIdx.x;
    const int lane = tid & 31;
    const int wid  = tid >> 5;
    const size_t base = (size_t)blockIdx.x * T_LEN;

    // flags must be reset every launch (graph replays reuse stale smem)
    if (tid < NWARP) flag[tid] = 0;
    __syncthreads();                  // only block-wide barrier in the kernel

    // ---- warp-local async load: one ascending sweep, TWO commit groups ----
    // iterations 0-7  -> rows 0-15  (lanes 0-15's pass-1 rows)  -> group 0
    // iterations 8-15 -> rows 16-31 (lanes 16-31's pass-1 rows) -> group 1
    const int wbase = wid * WSEG;
    #pragma unroll
    for (int k = 0; k < 8; k++) {
        int i4 = wbase + k * (32 * 4) + 4 * lane;    // 16B aligned
        cp_async16(s_buf + PAD(i4), x + base + i4);
    }
    asm volatile("cp.async.commit_group;");
    #pragma unroll
    for (int k = 8; k < 16; k++) {
        int i4 = wbase + k * (32 * 4) + 4 * lane;
        cp_async16(s_buf + PAD(i4), x + base + i4);
    }
    asm volatile("cp.async.commit_group;");

    // ---- pass 1, staggered: lanes 0-15 start after the first 4KB ----
    const int t0 = tid * KP;
    const float4* row = reinterpret_cast<const float4*>(s_buf + PAD(t0));
    float a0 = 0.f, b0 = 0.f, a1 = 0.f, b1 = 0.f;

    asm volatile("cp.async.wait_group 1;" ::: "memory");
    __syncwarp();                     // all lanes' group-0 writes visible
    if (lane < 16)
        warm_unroll<0>(row, a0, b0, a1, b1);

    asm volatile("cp.async.wait_group 0;" ::: "memory");
    __syncwarp();                     // all lanes' group-1 writes visible
    if (lane >= 16)
        warm_unroll<0>(row, a0, b0, a1, b1);

    float L1 = a0 + a1;
    float L2 = b0 + b1;

    // ---- in-warp affine inclusive scan: combine = vR + mR*vL ----
    float v1 = L1, v2 = L2, m = A64_F;
    #pragma unroll
    for (int d = 1; d < 32; d <<= 1) {
        float pv1 = __shfl_up_sync(0xffffffffu, v1, d);
        float pv2 = __shfl_up_sync(0xffffffffu, v2, d);
        float pm  = __shfl_up_sync(0xffffffffu, m,  d);
        if (lane >= d) {
            v1 = fmaf(m, pv1, v1);
            v2 = fmaf(m, pv2, v2);
            m *= pm;
        }
    }
    float ev1 = __shfl_up_sync(0xffffffffu, v1, 1);
    float ev2 = __shfl_up_sync(0xffffffffu, v2, 1);
    float em  = __shfl_up_sync(0xffffffffu, m,  1);
    if (lane == 0) { ev1 = 0.f; ev2 = 0.f; em = 1.f; }

    // ---- cross-warp prefix: flag-chained relay through smem ----
    float p1 = 0.f, p2 = 0.f, pm = 1.f;
    if (wid > 0) {
        if (lane == 0) { while (flag[wid - 1] == 0) {} }
        __syncwarp();
        __threadfence_block();
        p1 = pub1[wid - 1]; p2 = pub2[wid - 1]; pm = pubm[wid - 1];
    }
    if (wid < NWARP - 1 && lane == 31) {
        // this warp's inclusive prefix = own total (v,m at lane31) ∘ prefix
        pub1[wid] = fmaf(m, p1, v1);
        pub2[wid] = fmaf(m, p2, v2);
        pubm[wid] = m * pm;
        __threadfence_block();
        flag[wid] = 1;
    }

    // thread's exact start state
    float s1 = fmaf(em, p1, ev1);
    float s2 = fmaf(em, p2, ev2);
    float w  = 1.0f - pm * em;        // == 1.0f exactly for tid >= 28

    // ---- pass 2: normalize 64 steps from exact state, in-place ----
    float4* rw = reinterpret_cast<float4*>(s_buf + PAD(t0));
    if (tid >= W1_TID) {
        #pragma unroll
        for (int i = 0; i < KP / 4; i++) {
            float4 v = rw[i];
            float4 o;
            o.x = ema_step_1(v.x, s1, s2);
            o.y = ema_step_1(v.y, s1, s2);
            o.z = ema_step_1(v.z, s1, s2);
            o.w = ema_step_1(v.w, s1, s2);
            rw[i] = o;
        }
    } else {
        #pragma unroll
        for (int i = 0; i < KP / 4; i++) {
            float4 v = rw[i];
            float4 o;
            o.x = ema_step_w(v.x, s1, s2, w);
            o.y = ema_step_w(v.y, s1, s2, w);
            o.z = ema_step_w(v.z, s1, s2, w);
            o.w = ema_step_w(v.w, s1, s2, w);
            rw[i] = o;
        }
    }
    __syncwarp();                     // warp's region fully written

    // ---- warp-local coalesced store (streaming: y never re-read) ----
    #pragma unroll
    for (int k = 0; k < WSEG / (32 * 4); k++) {
        int i4 = wbase + k * (32 * 4) + 4 * lane;
        float4 v = *reinterpret_cast<const float4*>(s_buf + PAD(i4));
        __stcs(reinterpret_cast<float4*>(y + base + i4), v);
    }
}

extern "C" void kernel_launch(void* const* d_in, const int* in_sizes, int n_in,
                              void* d_out, int out_size) {
    const float* x = (const float*)d_in[0];
    float*       y = (float*)d_out;

    int total = in_sizes[0];            // B*C*T
    int lanes = total / T_LEN;          // 2048 blocks, one per lane

    cudaFuncSetAttribute(ema_norm_kernel,
                         cudaFuncAttributeMaxDynamicSharedMemorySize,
                         SMEM_F * sizeof(float));
    ema_norm_kernel<<<lanes, TPB, SMEM_F * sizeof(float)>>>(x, y);
}